// round 17
// baseline (speedup 1.0000x reference)
#include <cuda_runtime.h>
#include <cstddef>

// Problem constants (from reference)
#define BB       16     // batch
#define SS       256    // SU == SV
#define DEG      3      // P == Q
#define KLEN     132    // M + P + 2 == N + Q + 2
#define NCTRL    128    // M + 1 == N + 1
#define MAXSPAN  127    // M == N
#define NINNER   (KLEN - 2 * DEG)   // 126
#define EPSF     1e-8f
#define ROWS     4      // u-rows per block
#define VOFF     (SS - KLEN)        // 124: thread offset for Kv coverage

// ---------------------------------------------------------------------------
// Span + degree-3 Cox-de Boor basis for one parameter value, knots in smem.
// Exact fp ordering of the reference (first-min argmin, denom association,
// denom==0 -> 1e-4 branch).
// ---------------------------------------------------------------------------
__device__ __forceinline__ void span_basis(const float* __restrict__ K,
                                           float t, int& span, float* Nf)
{
    float best = 3.4e38f;
    int   bi   = 0;
    #pragma unroll 1
    for (int i = 0; i < NINNER; i++) {
        float d = t - K[DEG + i];
        float m = (d > EPSF) ? d : 1.0f;
        if (m < best) { best = m; bi = i; }
    }
    span = bi + DEG;
    if (span > MAXSPAN) span = MAXSPAN;
    if (span < DEG)     span = DEG;

    Nf[0] = 1.0f; Nf[1] = 0.0f; Nf[2] = 0.0f; Nf[3] = 0.0f;
    #pragma unroll
    for (int k = 1; k <= DEG; k++) {
        float saved = 0.0f;
        #pragma unroll
        for (int r = 0; r < k; r++) {
            float K1 = K[span + r + 1];
            float K2 = K[span + 1 - k + r];
            float denom = (K1 - t) + (t - K2);
            float temp  = (denom == 0.0f) ? 1e-4f : (Nf[r] / denom);
            Nf[r] = saved + (K1 - t) * temp;
            saved = (t - K2) * temp;
        }
        Nf[k] = saved;
    }
}

// ---------------------------------------------------------------------------
// Single fused kernel. Grid: (SS/ROWS, BB). Block: SS threads (one per v).
//
// Knot coverage (R13 bug fixed): 2*KLEN = 264 > 256 threads, so two
// INDEPENDENT predicates — threads [0,132) handle Ku, threads [124,256)
// handle Kv (8 threads do both; both arrays fully covered).
// ---------------------------------------------------------------------------
__global__ __launch_bounds__(SS)
void fused_kernel(const float* __restrict__ ctrl,
                  const float* __restrict__ knot_u,
                  const float* __restrict__ knot_v,
                  const float* __restrict__ uu,
                  const float* __restrict__ vv,
                  float* __restrict__ out)
{
    __shared__ float Ku[KLEN];
    __shared__ float Kv[KLEN];
    __shared__ float nrm[4];            // k0u, denu, k0v, denv
    __shared__ float uW[ROWS][DEG + 1]; // u weights
    __shared__ int   uS[ROWS];          // u spans
    __shared__ float srow[ROWS][NCTRL * 3];

    const int b   = blockIdx.y;
    const int iu0 = blockIdx.x * ROWS;
    const int tid = threadIdx.x;

    // ---- knots: load + clamp negatives (full coverage of BOTH arrays)
    if (tid < KLEN) {
        float x = knot_u[b * KLEN + tid];
        Ku[tid] = (x < 0.0f) ? 1e-4f : x;
    }
    if (tid >= VOFF) {                  // tid in [124, 256) -> Kv[0..131]
        int i = tid - VOFF;
        float x = knot_v[b * KLEN + i];
        Kv[i] = (x < 0.0f) ? 1e-4f : x;
    }
    __syncthreads();

    // ---- serial cumsum, exact reference order: lane 0 = U, lane 1 = V.
    // Loads are independent of prior stores -> only the FADD chain serial.
    if (tid < 2) {
        float* K = tid ? Kv : Ku;
        float acc = 0.0f;
        #pragma unroll 4
        for (int i = 0; i < KLEN; i++) { acc += K[i]; K[i] = acc; }
        nrm[tid * 2 + 0] = K[0];
        nrm[tid * 2 + 1] = K[KLEN - 1] - K[0];
    }
    __syncthreads();

    // ---- normalize (same coverage pattern)
    if (tid < KLEN) {
        Ku[tid] = (Ku[tid] - nrm[0]) / nrm[1];
    }
    if (tid >= VOFF) {
        int i = tid - VOFF;
        Kv[i] = (Kv[i] - nrm[2]) / nrm[3];
    }
    __syncthreads();

    // ---- v basis: one sample per thread, kept in registers
    int   sv;
    float qv[DEG + 1];
    span_basis(Kv, vv[tid], sv, qv);

    // ---- u basis: ROWS values on threads 0..ROWS-1 -> smem
    if (tid < ROWS) {
        int   su;
        float wu[DEG + 1];
        span_basis(Ku, uu[iu0 + tid], su, wu);
        uS[tid] = su;
        #pragma unroll
        for (int k = 0; k <= DEG; k++) uW[tid][k] = wu[k];
    }
    __syncthreads();

    // ---- Phase A: blend ROWS x 4 ctrl rows -> srow (float4-coalesced)
    #pragma unroll
    for (int i = tid; i < ROWS * (NCTRL * 3) / 4; i += SS) {
        const int r = i / ((NCTRL * 3) / 4);
        const int j = i % ((NCTRL * 3) / 4);

        const int   su = uS[r];
        const float w0 = uW[r][0];
        const float w1 = uW[r][1];
        const float w2 = uW[r][2];
        const float w3 = uW[r][3];

        const float4* c0 =
            (const float4*)(ctrl + ((size_t)b * NCTRL + (size_t)(su - DEG)) * (NCTRL * 3));

        float4 a  = c0[j];
        float4 p  = c0[j +     (NCTRL * 3) / 4];
        float4 q  = c0[j + 2 * (NCTRL * 3) / 4];
        float4 rr = c0[j + 3 * (NCTRL * 3) / 4];
        float4 s;
        s.x = w0 * a.x + w1 * p.x + w2 * q.x + w3 * rr.x;
        s.y = w0 * a.y + w1 * p.y + w2 * q.y + w3 * rr.y;
        s.z = w0 * a.z + w1 * p.z + w2 * q.z + w3 * rr.z;
        s.w = w0 * a.w + w1 * p.w + w2 * q.w + w3 * rr.w;
        ((float4*)srow[r])[j] = s;
    }
    __syncthreads();

    // ---- Phase B: 4-tap v reduction, direct global stores
    {
        const int o = (sv - DEG) * 3;
        #pragma unroll
        for (int r = 0; r < ROWS; r++) {
            float* orow = out + (((size_t)b * SS + (size_t)(iu0 + r)) * SS + tid) * 3;
            #pragma unroll
            for (int d = 0; d < 3; d++) {
                orow[d] = qv[0] * srow[r][o + d]
                        + qv[1] * srow[r][o + 3 + d]
                        + qv[2] * srow[r][o + 6 + d]
                        + qv[3] * srow[r][o + 9 + d];
            }
        }
    }
}

// ---------------------------------------------------------------------------
// Launch. Inputs (metadata order): ctrl_pts, knot_u, knot_v, u, v
// ---------------------------------------------------------------------------
extern "C" void kernel_launch(void* const* d_in, const int* in_sizes, int n_in,
                              void* d_out, int out_size)
{
    const float* ctrl = (const float*)d_in[0];   // (16,128,128,3)
    const float* ku   = (const float*)d_in[1];   // (16,132)
    const float* kv   = (const float*)d_in[2];   // (16,132)
    const float* u    = (const float*)d_in[3];   // (256,)
    const float* v    = (const float*)d_in[4];   // (256,)
    float*       out  = (float*)d_out;           // (16,256,256,3)

    fused_kernel<<<dim3(SS / ROWS, BB), SS>>>(ctrl, ku, kv, u, v, out);
}